// round 1
// baseline (speedup 1.0000x reference)
#include <cuda_runtime.h>
#include <cstdint>
#include <cstddef>

#define RES_C     128
#define SKIP_CC   128
#define BATCH     4
#define T_START   8192
#define NBLK      40
#define SKIP_SIZE 4096

#define TN   64          // timesteps per CTA
#define LDX  72          // pitch (floats) for X and G tiles (conflict-free for B frags)
#define LDW  36          // pitch (floats) for weight chunks (conflict-free for A frags)
#define KC   32          // K per weight chunk

#define SX_FLOATS (256 * LDX)          // 18432
#define SG_FLOATS (128 * LDX)          //  9216
#define SW_FLOATS (256 * LDW)          //  9216 (per buffer)
#define SMEM_FLOATS (SX_FLOATS + SG_FLOATS + 2 * SW_FLOATS)
#define SMEM_BYTES  (SMEM_FLOATS * 4)  // 184320 B

static const int H_DIL[NBLK] = {
    1,2,4,8,16,32,64,128,256,512,
    1,2,4,8,16,32,64,128,256,512,
    1,2,4,8,16,32,64,128,256,512,
    1,2,4,8,16,32,64,128,256,512};

// ---------------- device scratch (no runtime allocation allowed) ----------------
__device__ float g_bufA[BATCH * RES_C * T_START];   // 16.8 MB ping
__device__ float g_bufB[BATCH * RES_C * T_START];   // 16.8 MB pong
__device__ float g_wcat[NBLK * 128 * 256];          // stage-1 weights [blk][o][k], k<128->W0, k>=128->W1
__device__ float g_w2[NBLK * 256 * 128];            // stage-2 weights [blk][ro][k], ro<128->res, else skip

// ---------------- helpers ----------------
__device__ __forceinline__ float to_tf32(float x) {
    uint32_t u;
    asm("cvt.rna.tf32.f32 %0, %1;" : "=r"(u) : "f"(x));
    return __uint_as_float(u);
}

__device__ __forceinline__ void mma_tf32(float c[4], const uint32_t a[4], const uint32_t b[2]) {
    asm volatile(
        "mma.sync.aligned.m16n8k8.row.col.f32.tf32.tf32.f32 "
        "{%0,%1,%2,%3}, {%4,%5,%6,%7}, {%8,%9}, {%0,%1,%2,%3};\n"
        : "+f"(c[0]), "+f"(c[1]), "+f"(c[2]), "+f"(c[3])
        : "r"(a[0]), "r"(a[1]), "r"(a[2]), "r"(a[3]), "r"(b[0]), "r"(b[1]));
}

// Numerically stable tanh(y)*sigmoid(y) with a single __expf.
__device__ __forceinline__ float gate_fn(float y) {
    float ay = fabsf(y);
    float u  = __expf(-ay);          // (0, 1]
    float u2 = u * u;                // e^{-2|y|}
    float th = (1.f - u2) / (1.f + u2);   // tanh(|y|)
    float sg = 1.f / (1.f + u);           // sigmoid(|y|)
    float s  = (y >= 0.f) ? sg : (1.f - sg);
    float t  = (y >= 0.f) ? th : -th;
    return t * s;
}

// ---------------- weight prep kernels (run every call; deterministic) ----------------
__global__ void prep_wdil_k(const float* __restrict__ w, float* __restrict__ out, int n) {
    int i = blockIdx.x * blockDim.x + threadIdx.x;
    if (i >= n) return;
    int k   = i & 255;          // 0..255
    int o   = (i >> 8) & 127;   // 0..127
    int blk = i >> 15;          // 0..39
    // src: w_dil[blk][o][k&127][k>>7]  (shape [40,128,128,2])
    float v = w[(((blk * 128 + o) * 128) + (k & 127)) * 2 + (k >> 7)];
    out[i] = to_tf32(v);
}

__global__ void prep_w2_k(const float* __restrict__ wr, const float* __restrict__ ws,
                          float* __restrict__ out, int n) {
    int i = blockIdx.x * blockDim.x + threadIdx.x;
    if (i >= n) return;
    int k   = i & 127;          // 0..127
    int ro  = (i >> 7) & 255;   // 0..255
    int blk = i >> 15;          // 0..39
    float v = (ro < 128) ? wr[((blk * 128 + ro) * 128) + k]
                         : ws[((blk * 128 + (ro - 128)) * 128) + k];
    out[i] = to_tf32(v);
}

// ---------------- fused per-block kernel ----------------
// Stage 1: Y[128,TN] = Wcat[128,256] @ [Xa;Xb][256,TN], gate -> G (smem)
// Stage 2: [R;S][256,TN] = W2[256,128] @ G[128,TN]
// Epilogue: xout = R + b_res + x[t+d] ; skip window write = S + b_skip
__global__ __launch_bounds__(256, 1)
void wavenet_block(const float* __restrict__ xin, float* __restrict__ xout,
                   float* __restrict__ skip,
                   const float* __restrict__ wcat, const float* __restrict__ w2,
                   const float* __restrict__ brs, const float* __restrict__ bsk,
                   int Tc, int d, int L, int sstart)
{
    extern __shared__ float smem[];
    float* sX = smem;                  // [256][LDX]
    float* sG = sX + SX_FLOATS;        // [128][LDX]
    float* sW = sG + SG_FLOATS;        // 2 x [256][LDW]

    const int tid  = threadIdx.x;
    const int lane = tid & 31;
    const int wid  = tid >> 5;
    const int g    = lane >> 2;
    const int tg   = lane & 3;
    const int t0   = blockIdx.x * TN;
    const int b    = blockIdx.y;

    // warp tiling: stage1 = 4x2 warp grid (32x32 each); stage2 = 8x1 (32x64 each)
    const int wm1 = (wid >> 1) << 5;
    const int wn1 = (wid & 1) << 5;
    const int wm2 = wid << 5;

    // ---- cp.async fetch of weight K-chunk idx into buffer (idx&1) ----
    auto fetch = [&](int idx) {
        const float* src;
        int R, stride, kc;
        if (idx < 8) { src = wcat; R = 128; stride = 256; kc = idx * KC; }
        else         { src = w2;   R = 256; stride = 128; kc = (idx - 8) * KC; }
        float* dst = sW + (idx & 1) * SW_FLOATS;
        const int n16 = R * 8;  // 16B units per chunk row: 32 floats = 8 x float4
        for (int i = tid; i < n16; i += 256) {
            int r = i >> 3;
            int j = (i & 7) << 2;
            uint32_t sa = (uint32_t)__cvta_generic_to_shared(dst + r * LDW + j);
            const float* gp = src + (size_t)r * stride + kc + j;
            asm volatile("cp.async.cg.shared.global [%0], [%1], 16;\n" :: "r"(sa), "l"(gp));
        }
        asm volatile("cp.async.commit_group;\n");
    };

    fetch(0);

    // ---- load X tile (tf32-rounded): rows 0..127 = x[t], rows 128..255 = x[t+d] ----
    {
        const float* xb = xin + (size_t)b * RES_C * Tc;
        for (int i = tid; i < 256 * TN; i += 256) {
            int r = i >> 6;        // row 0..255
            int t = i & (TN - 1);  // 0..63
            float v = 0.f;
            int tt = t0 + t;
            if (r < 128) {
                if (tt < Tc) v = xb[(size_t)r * Tc + tt];
            } else {
                if (tt < L)  v = xb[(size_t)(r - 128) * Tc + tt + d];
            }
            sX[r * LDX + t] = to_tf32(v);
        }
    }

    float acc1[2][4][4];
    float acc2[2][8][4];
    #pragma unroll
    for (int i = 0; i < 2; ++i)
        #pragma unroll
        for (int j = 0; j < 4; ++j)
            #pragma unroll
            for (int q = 0; q < 4; ++q) acc1[i][j][q] = 0.f;
    #pragma unroll
    for (int i = 0; i < 2; ++i)
        #pragma unroll
        for (int j = 0; j < 8; ++j)
            #pragma unroll
            for (int q = 0; q < 4; ++q) acc2[i][j][q] = 0.f;

    // ---- main pipeline over 12 weight chunks (8 stage-1, 4 stage-2) ----
    for (int c = 0; c < 12; ++c) {
        if (c + 1 < 12) {
            fetch(c + 1);
            asm volatile("cp.async.wait_group 1;\n");
        } else {
            asm volatile("cp.async.wait_group 0;\n");
        }
        __syncthreads();   // chunk c visible to all; X/G visible

        const float* Wb = sW + (c & 1) * SW_FLOATS;

        if (c < 8) {
            // ---- stage 1: accumulate Y over K-chunk ----
            const int kc = c << 5;
            #pragma unroll
            for (int s = 0; s < 4; ++s) {
                const int k = s << 3;
                uint32_t a[2][4];
                #pragma unroll
                for (int mt = 0; mt < 2; ++mt) {
                    const float* A = Wb + (wm1 + mt * 16 + g) * LDW + k + tg;
                    a[mt][0] = __float_as_uint(A[0]);
                    a[mt][1] = __float_as_uint(A[8 * LDW]);
                    a[mt][2] = __float_as_uint(A[4]);
                    a[mt][3] = __float_as_uint(A[8 * LDW + 4]);
                }
                uint32_t bb[4][2];
                #pragma unroll
                for (int nt = 0; nt < 4; ++nt) {
                    const float* B = sX + (kc + k + tg) * LDX + wn1 + nt * 8 + g;
                    bb[nt][0] = __float_as_uint(B[0]);
                    bb[nt][1] = __float_as_uint(B[4 * LDX]);
                }
                #pragma unroll
                for (int mt = 0; mt < 2; ++mt)
                    #pragma unroll
                    for (int nt = 0; nt < 4; ++nt)
                        mma_tf32(acc1[mt][nt], a[mt], bb[nt]);
            }
            if (c == 7) {
                // ---- gate Y -> G (tf32) ----
                #pragma unroll
                for (int mt = 0; mt < 2; ++mt)
                    #pragma unroll
                    for (int nt = 0; nt < 4; ++nt) {
                        float* cc = acc1[mt][nt];
                        int r0 = wm1 + mt * 16 + g;
                        int c0 = wn1 + nt * 8 + (tg << 1);
                        sG[r0 * LDX + c0]           = to_tf32(gate_fn(cc[0]));
                        sG[r0 * LDX + c0 + 1]       = to_tf32(gate_fn(cc[1]));
                        sG[(r0 + 8) * LDX + c0]     = to_tf32(gate_fn(cc[2]));
                        sG[(r0 + 8) * LDX + c0 + 1] = to_tf32(gate_fn(cc[3]));
                    }
            }
        } else {
            // ---- stage 2: [R;S] = W2 @ G over K-chunk ----
            const int kc = (c - 8) << 5;
            #pragma unroll
            for (int s = 0; s < 4; ++s) {
                const int k = s << 3;
                uint32_t a[2][4];
                #pragma unroll
                for (int mt = 0; mt < 2; ++mt) {
                    const float* A = Wb + (wm2 + mt * 16 + g) * LDW + k + tg;
                    a[mt][0] = __float_as_uint(A[0]);
                    a[mt][1] = __float_as_uint(A[8 * LDW]);
                    a[mt][2] = __float_as_uint(A[4]);
                    a[mt][3] = __float_as_uint(A[8 * LDW + 4]);
                }
                uint32_t bb[8][2];
                #pragma unroll
                for (int nt = 0; nt < 8; ++nt) {
                    const float* B = sG + (kc + k + tg) * LDX + nt * 8 + g;
                    bb[nt][0] = __float_as_uint(B[0]);
                    bb[nt][1] = __float_as_uint(B[4 * LDX]);
                }
                #pragma unroll
                for (int mt = 0; mt < 2; ++mt)
                    #pragma unroll
                    for (int nt = 0; nt < 8; ++nt)
                        mma_tf32(acc2[mt][nt], a[mt], bb[nt]);
            }
        }
        __syncthreads();   // protect buffer (c+1)&1 reuse and sG publication
    }

    // ---- epilogue: residual + bias + skip-window writes ----
    const float* xb = xin + (size_t)b * RES_C * Tc;
    #pragma unroll
    for (int mt = 0; mt < 2; ++mt) {
        #pragma unroll
        for (int half = 0; half < 2; ++half) {
            const int ro = wm2 + mt * 16 + g + half * 8;
            #pragma unroll
            for (int nt = 0; nt < 8; ++nt) {
                float v0 = acc2[mt][nt][half * 2 + 0];
                float v1 = acc2[mt][nt][half * 2 + 1];
                int col = nt * 8 + (tg << 1);
                int t = t0 + col;
                if (ro < 128) {
                    float base = brs[ro];
                    if (t < L)
                        xout[((size_t)b * 128 + ro) * L + t]     = v0 + base + xb[(size_t)ro * Tc + t + d];
                    if (t + 1 < L)
                        xout[((size_t)b * 128 + ro) * L + t + 1] = v1 + base + xb[(size_t)ro * Tc + t + 1 + d];
                } else {
                    const int o = ro - 128;
                    float base = bsk[o];
                    if (t >= sstart && t < L)
                        skip[((size_t)b * 128 + o) * SKIP_SIZE + (t - sstart)]     = v0 + base;
                    if (t + 1 >= sstart && t + 1 < L)
                        skip[((size_t)b * 128 + o) * SKIP_SIZE + (t + 1 - sstart)] = v1 + base;
                }
            }
        }
    }
}

// ---------------- host launcher ----------------
extern "C" void kernel_launch(void* const* d_in, const int* in_sizes, int n_in,
                              void* d_out, int out_size) {
    (void)in_sizes; (void)n_in; (void)out_size;

    const float* x     = (const float*)d_in[0];
    const float* wdil  = (const float*)d_in[1];
    const float* wres  = (const float*)d_in[2];
    const float* bres  = (const float*)d_in[3];
    const float* wskip = (const float*)d_in[4];
    const float* bskip = (const float*)d_in[5];
    float* out = (float*)d_out;

    float *bufA, *bufB, *wcat, *w2;
    cudaGetSymbolAddress((void**)&bufA, g_bufA);
    cudaGetSymbolAddress((void**)&bufB, g_bufB);
    cudaGetSymbolAddress((void**)&wcat, g_wcat);
    cudaGetSymbolAddress((void**)&w2,   g_w2);

    cudaFuncSetAttribute(wavenet_block, cudaFuncAttributeMaxDynamicSharedMemorySize, SMEM_BYTES);

    const int n1 = NBLK * 128 * 256;   // == NBLK*256*128
    prep_wdil_k<<<(n1 + 255) / 256, 256>>>(wdil, wcat, n1);
    prep_w2_k<<<(n1 + 255) / 256, 256>>>(wres, wskip, w2, n1);

    int Tc = T_START;
    const float* cur = x;
    float* nxt = bufA;
    for (int blk = 0; blk < NBLK; ++blk) {
        const int d = H_DIL[blk];
        const int L = Tc - d;
        dim3 grid((L + TN - 1) / TN, BATCH);
        wavenet_block<<<grid, 256, SMEM_BYTES>>>(
            cur, nxt,
            out + (size_t)blk * BATCH * SKIP_CC * SKIP_SIZE,
            wcat + (size_t)blk * 128 * 256,
            w2   + (size_t)blk * 256 * 128,
            bres + blk * 128, bskip + blk * 128,
            Tc, d, L, L - SKIP_SIZE);
        cur = nxt;
        nxt = (nxt == bufA) ? bufB : bufA;
        Tc = L;
    }
}

// round 3
// speedup vs baseline: 1.5813x; 1.5813x over previous
#include <cuda_runtime.h>
#include <cstdint>
#include <cstddef>

#define RES_C     128
#define BATCH     4
#define T_START   8192
#define NBLK      40
#define SKIP_SIZE 4096

#define TN        128          // timesteps per CTA
#define NTHREADS  512          // 16 warps

#define XP        260          // X pitch (floats): 256 + 4  (≡4 mod 32 -> conflict-free frags)
#define GP        132          // G pitch: 128 + 4
#define W1P       68           // stage-1 weight chunk pitch (64 + 4)
#define W2P       36           // stage-2 weight chunk pitch (32 + 4)
#define STP       132          // epilogue transpose pitch (≡4 mod 32; 2tg*132+g -> 8tg+g bijective)

#define X_FLOATS  (128 * XP)               // 33280
#define WBUF_FLOATS 9216                   // 36864 B per buffer (fits both chunk kinds)
#define SMEM_FLOATS (X_FLOATS + 2 * WBUF_FLOATS)
#define SMEM_BYTES  (SMEM_FLOATS * 4)      // 206848

#define W1_CHUNK_FLOATS (128 * W1P)        // 8704  (34816 B)
#define W2_CHUNK_FLOATS (256 * W2P)        // 9216  (36864 B)
#define W1_BLK_FLOATS   (4 * W1_CHUNK_FLOATS)
#define W2_BLK_FLOATS   (4 * W2_CHUNK_FLOATS)

static const int H_DIL[NBLK] = {
    1,2,4,8,16,32,64,128,256,512,
    1,2,4,8,16,32,64,128,256,512,
    1,2,4,8,16,32,64,128,256,512,
    1,2,4,8,16,32,64,128,256,512};

// ---------------- device scratch ----------------
__device__ float g_bufA[BATCH * RES_C * T_START];
__device__ float g_bufB[BATCH * RES_C * T_START];
__device__ float g_w1[NBLK * W1_BLK_FLOATS];   // [blk][chunk4][out128][W1P]
__device__ float g_w2[NBLK * W2_BLK_FLOATS];   // [blk][chunk4][row256][W2P] rows<128 res, >=128 skip

// ---------------- helpers ----------------
__device__ __forceinline__ uint32_t tf32u(float x) {
    uint32_t u;
    asm("cvt.rna.tf32.f32 %0, %1;" : "=r"(u) : "f"(x));
    return u;
}
__device__ __forceinline__ float tf32f(float x) { return __uint_as_float(tf32u(x)); }

__device__ __forceinline__ void mma_tf32(float c[4], const uint32_t a[4], const uint32_t b[2]) {
    asm volatile(
        "mma.sync.aligned.m16n8k8.row.col.f32.tf32.tf32.f32 "
        "{%0,%1,%2,%3}, {%4,%5,%6,%7}, {%8,%9}, {%0,%1,%2,%3};\n"
        : "+f"(c[0]), "+f"(c[1]), "+f"(c[2]), "+f"(c[3])
        : "r"(a[0]), "r"(a[1]), "r"(a[2]), "r"(a[3]), "r"(b[0]), "r"(b[1]));
}

__device__ __forceinline__ float gate_fn(float y) {
    float ay = fabsf(y);
    float u  = __expf(-ay);
    float u2 = u * u;
    float th = (1.f - u2) / (1.f + u2);
    float sg = 1.f / (1.f + u);
    float s  = (y >= 0.f) ? sg : (1.f - sg);
    float t  = (y >= 0.f) ? th : -th;
    return t * s;
}

// ---------------- weight prep ----------------
// g_w1[blk][c][out][j]: j<64 -> W(out, k=64c+j) where k<128 => w_dil[...][k][0], k>=128 => w_dil[...][k-128][1]
__global__ void prep_w1(const float* __restrict__ w, float* __restrict__ out, int n) {
    int i = blockIdx.x * blockDim.x + threadIdx.x;
    if (i >= n) return;
    int blk = i / W1_BLK_FLOATS;
    int rem = i - blk * W1_BLK_FLOATS;
    int c   = rem / W1_CHUNK_FLOATS;
    int rr  = rem - c * W1_CHUNK_FLOATS;
    int o   = rr / W1P;
    int j   = rr - o * W1P;
    float v = 0.f;
    if (j < 64) {
        int k = c * 64 + j;
        v = (k < 128) ? w[(((blk * 128 + o) * 128) + k) * 2 + 0]
                      : w[(((blk * 128 + o) * 128) + (k - 128)) * 2 + 1];
    }
    out[i] = tf32f(v);
}
// g_w2[blk][c][row][j]: j<32 -> row<128 ? w_res[row][k=32c+j] : w_skip[row-128][k]
__global__ void prep_w2(const float* __restrict__ wr, const float* __restrict__ ws,
                        float* __restrict__ out, int n) {
    int i = blockIdx.x * blockDim.x + threadIdx.x;
    if (i >= n) return;
    int blk = i / W2_BLK_FLOATS;
    int rem = i - blk * W2_BLK_FLOATS;
    int c   = rem / W2_CHUNK_FLOATS;
    int rr  = rem - c * W2_CHUNK_FLOATS;
    int row = rr / W2P;
    int j   = rr - row * W2P;
    float v = 0.f;
    if (j < 32) {
        int k = c * 32 + j;
        v = (row < 128) ? wr[((blk * 128 + row) * 128) + k]
                        : ws[((blk * 128 + (row - 128)) * 128) + k];
    }
    out[i] = tf32f(v);
}

// ---------------- fused per-block kernel ----------------
// Orientation: A = activations (time-major), B = weights.
// Stage 1: Y[t 128][out 128] = X[t 128][k 256] * W1^T ; gate -> G[t][128] (aliased over X)
// Stage 2: [R|S][t 128][out 256] = G[t][k 128] * W2^T
__global__ __launch_bounds__(NTHREADS, 1)
void wavenet_block(const float* __restrict__ xin, float* __restrict__ xout,
                   float* __restrict__ skip,
                   const float* __restrict__ w1g, const float* __restrict__ w2g,
                   const float* __restrict__ brs, const float* __restrict__ bsk,
                   int Tc, int d, int L, int sstart)
{
    extern __shared__ float sm[];
    float* Xs = sm;                 // [128][XP]; aliased by G [128][GP] and ST [128][STP]
    float* Wb = sm + X_FLOATS;      // 2 x WBUF_FLOATS

    const int tid  = threadIdx.x;
    const int lane = tid & 31;
    const int wid  = tid >> 5;
    const int g    = lane >> 2;
    const int tg   = lane & 3;
    const int t0   = blockIdx.x * TN;
    const int b    = blockIdx.y;

    // 16 warps: 4 time-rows x 4 out-cols
    const int wm  = (wid & 3) * 32;        // time rows (stage1 & stage2)
    const int wn1 = (wid >> 2) * 32;       // stage1 out cols (nt=4)
    const int wn2 = (wid >> 2) * 64;       // stage2 out cols (nt=8)

    // ---- cp.async weight chunk fetch (contiguous) ----
    auto fetch = [&](int c) {
        const float* src;
        int n16;
        if (c < 4) { src = w1g + c * W1_CHUNK_FLOATS; n16 = W1_CHUNK_FLOATS / 4; }
        else       { src = w2g + (c - 4) * W2_CHUNK_FLOATS; n16 = W2_CHUNK_FLOATS / 4; }
        float* dst = Wb + (c & 1) * WBUF_FLOATS;
        for (int i = tid; i < n16; i += NTHREADS) {
            uint32_t sa = (uint32_t)__cvta_generic_to_shared(dst + i * 4);
            asm volatile("cp.async.cg.shared.global [%0], [%1], 16;\n" :: "r"(sa), "l"(src + i * 4));
        }
        asm volatile("cp.async.commit_group;\n");
    };

    fetch(0);
    fetch(1);

    // ---- X tile load (time-major, tf32): Xs[t][k], k<128 -> x[k][t], k>=128 -> x[k-128][t+d] ----
    const float* xb = xin + (size_t)b * RES_C * Tc;
    {
        const int t   = tid & 127;
        const int grp = tid >> 7;        // 0..3, each handles 64 k's
        const int tt  = t0 + t;
        float* xrow = Xs + t * XP;
        #pragma unroll
        for (int kk = 0; kk < 64; kk += 4) {
            const int k0 = grp * 64 + kk;
            uint32_t u[4];
            #pragma unroll
            for (int j = 0; j < 4; ++j) {
                const int k = k0 + j;
                float v = 0.f;
                if (k < 128) { if (tt < Tc) v = xb[(size_t)k * Tc + tt]; }
                else         { if (tt < L)  v = xb[(size_t)(k - 128) * Tc + tt + d]; }
                u[j] = tf32u(v);
            }
            uint32_t sa = (uint32_t)__cvta_generic_to_shared(xrow + k0);
            asm volatile("st.shared.v4.b32 [%0], {%1,%2,%3,%4};"
                         :: "r"(sa), "r"(u[0]), "r"(u[1]), "r"(u[2]), "r"(u[3]));
        }
    }

    // ================= stage 1: 4 phases of KC=64 =================
    float acc1[2][4][4];
    #pragma unroll
    for (int i = 0; i < 2; ++i)
        #pragma unroll
        for (int j = 0; j < 4; ++j)
            #pragma unroll
            for (int q = 0; q < 4; ++q) acc1[i][j][q] = 0.f;

    for (int p = 0; p < 4; ++p) {
        asm volatile("cp.async.wait_group 1;\n");
        __syncthreads();
        const float* W = Wb + (p & 1) * WBUF_FLOATS;
        const int kbase = p * 64;
        #pragma unroll
        for (int ks = 0; ks < 8; ++ks) {
            const int k = ks * 8;
            uint32_t a[2][4];
            #pragma unroll
            for (int mt = 0; mt < 2; ++mt) {
                const float* Ap = Xs + (size_t)(wm + mt * 16 + g) * XP + kbase + k + tg;
                a[mt][0] = __float_as_uint(Ap[0]);
                a[mt][1] = __float_as_uint(Ap[8 * XP]);
                a[mt][2] = __float_as_uint(Ap[4]);
                a[mt][3] = __float_as_uint(Ap[8 * XP + 4]);
            }
            uint32_t bb[4][2];
            #pragma unroll
            for (int nt = 0; nt < 4; ++nt) {
                const float* Bp = W + (size_t)(wn1 + nt * 8 + g) * W1P + k + tg;
                bb[nt][0] = __float_as_uint(Bp[0]);
                bb[nt][1] = __float_as_uint(Bp[4]);
            }
            #pragma unroll
            for (int mt = 0; mt < 2; ++mt)
                #pragma unroll
                for (int nt = 0; nt < 4; ++nt)
                    mma_tf32(acc1[mt][nt], a[mt], bb[nt]);
        }
        __syncthreads();
        fetch(p + 2);
    }

    // ---- gate: acc1 -> G[t][out] (aliased over Xs; stage-1 X reads are done) ----
    {
        float* G = Xs;   // pitch GP
        #pragma unroll
        for (int mt = 0; mt < 2; ++mt)
            #pragma unroll
            for (int nt = 0; nt < 4; ++nt) {
                const int t = wm + mt * 16 + g;
                const int o = wn1 + nt * 8 + 2 * tg;
                float* cc = acc1[mt][nt];
                G[(size_t)t * GP + o]           = tf32f(gate_fn(cc[0]));
                G[(size_t)t * GP + o + 1]       = tf32f(gate_fn(cc[1]));
                G[(size_t)(t + 8) * GP + o]     = tf32f(gate_fn(cc[2]));
                G[(size_t)(t + 8) * GP + o + 1] = tf32f(gate_fn(cc[3]));
            }
    }
    __syncthreads();

    // ================= stage 2: 4 phases of KC=32 =================
    float acc2[2][8][4];
    #pragma unroll
    for (int i = 0; i < 2; ++i)
        #pragma unroll
        for (int j = 0; j < 8; ++j)
            #pragma unroll
            for (int q = 0; q < 4; ++q) acc2[i][j][q] = 0.f;

    for (int p = 4; p < 8; ++p) {
        if (p < 7) asm volatile("cp.async.wait_group 1;\n");
        else       asm volatile("cp.async.wait_group 0;\n");
        __syncthreads();
        const float* W = Wb + (p & 1) * WBUF_FLOATS;
        const float* G = Xs;
        const int kbase = (p - 4) * 32;
        #pragma unroll
        for (int ks = 0; ks < 4; ++ks) {
            const int k = ks * 8;
            uint32_t a[2][4];
            #pragma unroll
            for (int mt = 0; mt < 2; ++mt) {
                const float* Ap = G + (size_t)(wm + mt * 16 + g) * GP + kbase + k + tg;
                a[mt][0] = __float_as_uint(Ap[0]);
                a[mt][1] = __float_as_uint(Ap[8 * GP]);
                a[mt][2] = __float_as_uint(Ap[4]);
                a[mt][3] = __float_as_uint(Ap[8 * GP + 4]);
            }
            uint32_t bb[8][2];
            #pragma unroll
            for (int nt = 0; nt < 8; ++nt) {
                const float* Bp = W + (size_t)(wn2 + nt * 8 + g) * W2P + k + tg;
                bb[nt][0] = __float_as_uint(Bp[0]);
                bb[nt][1] = __float_as_uint(Bp[4]);
            }
            #pragma unroll
            for (int mt = 0; mt < 2; ++mt)
                #pragma unroll
                for (int nt = 0; nt < 8; ++nt)
                    mma_tf32(acc2[mt][nt], a[mt], bb[nt]);
        }
        __syncthreads();
        if (p + 2 < 8) fetch(p + 2);
    }

    // ================= epilogue: two conflict-free transpose passes =================
    float* ST = Xs;   // pitch STP; G dead now
    #pragma unroll
    for (int h = 0; h < 2; ++h) {
        if ((wid >> 3) == h) {   // warps owning out columns [h*128, h*128+128)
            #pragma unroll
            for (int mt = 0; mt < 2; ++mt)
                #pragma unroll
                for (int nt = 0; nt < 8; ++nt) {
                    const int t = wm + mt * 16 + g;
                    const int o = wn2 + nt * 8 + 2 * tg - h * 128;
                    float* cc = acc2[mt][nt];
                    ST[(size_t)o * STP + t]           = cc[0];
                    ST[(size_t)(o + 1) * STP + t]     = cc[1];
                    ST[(size_t)o * STP + t + 8]       = cc[2];
                    ST[(size_t)(o + 1) * STP + t + 8] = cc[3];
                }
        }
        __syncthreads();

        const int t  = tid & 127;
        const int tt = t0 + t;
        if (h == 0) {
            if (tt < L) {
                for (int rr = tid >> 7; rr < 128; rr += 4)
                    xout[((size_t)b * 128 + rr) * L + tt] =
                        ST[(size_t)rr * STP + t] + __ldg(brs + rr) + xb[(size_t)rr * Tc + tt + d];
            }
        } else {
            if (tt >= sstart && tt < L) {
                for (int rr = tid >> 7; rr < 128; rr += 4)
                    skip[((size_t)b * 128 + rr) * SKIP_SIZE + (tt - sstart)] =
                        ST[(size_t)rr * STP + t] + __ldg(bsk + rr);
            }
        }
        __syncthreads();
    }
}

// ---------------- host launcher ----------------
extern "C" void kernel_launch(void* const* d_in, const int* in_sizes, int n_in,
                              void* d_out, int out_size) {
    (void)in_sizes; (void)n_in; (void)out_size;

    const float* x     = (const float*)d_in[0];
    const float* wdil  = (const float*)d_in[1];
    const float* wres  = (const float*)d_in[2];
    const float* bres  = (const float*)d_in[3];
    const float* wskip = (const float*)d_in[4];
    const float* bskip = (const float*)d_in[5];
    float* out = (float*)d_out;

    float *bufA, *bufB, *w1, *w2;
    cudaGetSymbolAddress((void**)&bufA, g_bufA);
    cudaGetSymbolAddress((void**)&bufB, g_bufB);
    cudaGetSymbolAddress((void**)&w1,   g_w1);
    cudaGetSymbolAddress((void**)&w2,   g_w2);

    cudaFuncSetAttribute(wavenet_block, cudaFuncAttributeMaxDynamicSharedMemorySize, SMEM_BYTES);

    const int n1 = NBLK * W1_BLK_FLOATS;
    const int n2 = NBLK * W2_BLK_FLOATS;
    prep_w1<<<(n1 + 255) / 256, 256>>>(wdil, w1, n1);
    prep_w2<<<(n2 + 255) / 256, 256>>>(wres, wskip, w2, n2);

    int Tc = T_START;
    const float* cur = x;
    float* nxt = bufA;
    for (int blk = 0; blk < NBLK; ++blk) {
        const int d = H_DIL[blk];
        const int L = Tc - d;
        dim3 grid((L + TN - 1) / TN, BATCH);
        wavenet_block<<<grid, NTHREADS, SMEM_BYTES>>>(
            cur, nxt,
            out + (size_t)blk * BATCH * RES_C * SKIP_SIZE,
            w1 + (size_t)blk * W1_BLK_FLOATS,
            w2 + (size_t)blk * W2_BLK_FLOATS,
            bres + blk * 128, bskip + blk * 128,
            Tc, d, L, L - SKIP_SIZE);
        cur = nxt;
        nxt = (nxt == bufA) ? bufB : bufA;
        Tc = L;
    }
}

// round 4
// speedup vs baseline: 1.5814x; 1.0001x over previous
#include <cuda_runtime.h>
#include <cstdint>
#include <cstddef>

#define RES_C     128
#define BATCH     4
#define T_START   8192
#define NBLK      40
#define SKIP_SIZE 4096

#define TN        128
#define NTHREADS  512           // 16 warps

#define XP        256           // X row pitch (floats), swizzled (no pad needed)
#define GPITCH    128           // G row pitch
#define STP       132           // epilogue transpose pitch

#define X_FLOATS      (128 * XP)        // 32768 (128KB)
#define CHUNK_FLOATS  8192              // 32KB per weight chunk (both stages)
#define NBUF          3
#define SMEM_BYTES    ((X_FLOATS + NBUF * CHUNK_FLOATS) * 4)   // 229376

#define W1_BLK_FLOATS (4 * CHUNK_FLOATS)
#define W2_BLK_FLOATS (4 * CHUNK_FLOATS)

static const int H_DIL[NBLK] = {
    1,2,4,8,16,32,64,128,256,512,
    1,2,4,8,16,32,64,128,256,512,
    1,2,4,8,16,32,64,128,256,512,
    1,2,4,8,16,32,64,128,256,512};

// ---------------- device scratch ----------------
__device__ float g_bufA[BATCH * RES_C * T_START];
__device__ float g_bufB[BATCH * RES_C * T_START];
__device__ float g_w1[NBLK * W1_BLK_FLOATS];   // pre-swizzled chunk images
__device__ float g_w2[NBLK * W2_BLK_FLOATS];

// ---------------- layout helpers ----------------
// pack: logical k -> packed col. k = 16P + tg + 4j  <->  c = 16P + 4tg + j
__host__ __device__ __forceinline__ int packc(int k) {
    return ((k >> 4) << 4) | ((k & 3) << 2) | ((k & 15) >> 2);
}
// per-row bank swizzle (bits 2..4 of the float-column index)
__host__ __device__ __forceinline__ int fsw(int r) {
    return ((r & 1) << 4) | ((r & 6) << 1);
}

__device__ __forceinline__ uint32_t tf32u(float x) {
    uint32_t u;
    asm("cvt.rna.tf32.f32 %0, %1;" : "=r"(u) : "f"(x));
    return u;
}
__device__ __forceinline__ float tf32f(float x) { return __uint_as_float(tf32u(x)); }

__device__ __forceinline__ void mma8(float c[4], uint32_t a0, uint32_t a1, uint32_t a2,
                                     uint32_t a3, uint32_t b0, uint32_t b1) {
    asm volatile(
        "mma.sync.aligned.m16n8k8.row.col.f32.tf32.tf32.f32 "
        "{%0,%1,%2,%3}, {%4,%5,%6,%7}, {%8,%9}, {%0,%1,%2,%3};\n"
        : "+f"(c[0]), "+f"(c[1]), "+f"(c[2]), "+f"(c[3])
        : "r"(a0), "r"(a1), "r"(a2), "r"(a3), "r"(b0), "r"(b1));
}

__device__ __forceinline__ void lds128(uint32_t r[4], uint32_t addr) {
    asm volatile("ld.shared.v4.b32 {%0,%1,%2,%3}, [%4];"
                 : "=r"(r[0]), "=r"(r[1]), "=r"(r[2]), "=r"(r[3]) : "r"(addr));
}

__device__ __forceinline__ float gate_fn(float y) {
    float ay = fabsf(y);
    float u  = __expf(-ay);
    float u2 = u * u;
    float th = (1.f - u2) / (1.f + u2);
    float sg = 1.f / (1.f + u);
    float s  = (y >= 0.f) ? sg : (1.f - sg);
    float t  = (y >= 0.f) ? th : -th;
    return t * s;
}

// ---------------- weight prep: packed+swizzled chunk images ----------------
// W1 chunk ch (KC=64): rows o in [0,128), pitch 64. dst col = packc(klocal) ^ fsw(o)
__global__ void prep_w1(const float* __restrict__ w, float* __restrict__ out, int n) {
    int i = blockIdx.x * blockDim.x + threadIdx.x;
    if (i >= n) return;
    int kl  = i & 63;
    int o   = (i >> 6) & 127;
    int ch  = (i >> 13) & 3;
    int blk = i >> 15;
    int kg  = ch * 64 + kl;
    float v = (kg < 128) ? w[(((blk * 128 + o) * 128) + kg) * 2 + 0]
                         : w[(((blk * 128 + o) * 128) + (kg - 128)) * 2 + 1];
    out[(size_t)blk * W1_BLK_FLOATS + ch * CHUNK_FLOATS + o * 64 + (packc(kl) ^ fsw(o))] = tf32f(v);
}
// W2 chunk ch (KC=32): rows ro in [0,256) (res then skip), pitch 32
__global__ void prep_w2(const float* __restrict__ wr, const float* __restrict__ ws,
                        float* __restrict__ out, int n) {
    int i = blockIdx.x * blockDim.x + threadIdx.x;
    if (i >= n) return;
    int kl  = i & 31;
    int ro  = (i >> 5) & 255;
    int ch  = (i >> 13) & 3;
    int blk = i >> 15;
    int kg  = ch * 32 + kl;
    float v = (ro < 128) ? wr[((blk * 128 + ro) * 128) + kg]
                         : ws[((blk * 128 + (ro - 128)) * 128) + kg];
    out[(size_t)blk * W2_BLK_FLOATS + ch * CHUNK_FLOATS + ro * 32 + (packc(kl) ^ fsw(ro))] = tf32f(v);
}

// ---------------- fused per-block kernel ----------------
__global__ __launch_bounds__(NTHREADS, 1)
void wavenet_block(const float* __restrict__ xin, float* __restrict__ xout,
                   float* __restrict__ skip,
                   const float* __restrict__ w1g, const float* __restrict__ w2g,
                   const float* __restrict__ brs, const float* __restrict__ bsk,
                   int Tc, int d, int L, int sstart)
{
    extern __shared__ float sm[];
    const uint32_t sXb = (uint32_t)__cvta_generic_to_shared(sm);
    const uint32_t sWb = sXb + X_FLOATS * 4;

    const int tid  = threadIdx.x;
    const int lane = tid & 31;
    const int wid  = tid >> 5;
    const int g    = lane >> 2;
    const int tg   = lane & 3;
    const int tg4  = tg << 2;
    const int fg   = fsw(g);          // fsw(g) == fsw(g+8): row-swizzle for all frag reads
    const int t0   = blockIdx.x * TN;
    const int b    = blockIdx.y;

    const int wm  = (wid & 3) * 32;   // time tile
    const int wn1 = (wid >> 2) * 32;  // stage-1 out tile
    const int wn2 = (wid >> 2) * 64;  // stage-2 out tile

    // ---- cp.async weight chunk fetch (linear 32KB) ----
    auto fetch = [&](int c) {
        const float* src = (c < 4) ? (w1g + c * CHUNK_FLOATS) : (w2g + (c - 4) * CHUNK_FLOATS);
        uint32_t dst = sWb + (uint32_t)(c % 3) * (CHUNK_FLOATS * 4);
        #pragma unroll
        for (int i = 0; i < 4; ++i) {
            int e = tid + i * NTHREADS;
            asm volatile("cp.async.cg.shared.global [%0], [%1], 16;\n"
                         :: "r"(dst + e * 16), "l"(src + e * 4));
        }
        asm volatile("cp.async.commit_group;\n");
    };

    fetch(0);
    fetch(1);

    // ---- X tile: packed+swizzled, tf32. row t, logical k: k<128 -> x[k][tt], else x[k-128][tt+d]
    const float* xb = xin + (size_t)b * RES_C * Tc;
    {
        const int t   = tid & 127;
        const int grp = tid >> 7;
        const int tt  = t0 + t;
        const int ft  = fsw(t);
        const uint32_t xrow = sXb + (uint32_t)t * (XP * 4);
        #pragma unroll
        for (int idx = 0; idx < 16; ++idx) {
            const int Pl   = idx >> 2;
            const int tgi  = idx & 3;
            const int cbase = grp * 64 + Pl * 16 + tgi * 4;
            const int kb    = grp * 64 + Pl * 16 + tgi;
            uint32_t u[4];
            #pragma unroll
            for (int j = 0; j < 4; ++j) {
                const int k = kb + 4 * j;
                float v = 0.f;
                if (k < 128) { if (tt < Tc) v = xb[(size_t)k * Tc + tt]; }
                else         { if (tt < L)  v = xb[(size_t)(k - 128) * Tc + tt + d]; }
                u[j] = tf32u(v);
            }
            uint32_t sa = xrow + (uint32_t)((cbase ^ ft) << 2);
            asm volatile("st.shared.v4.b32 [%0], {%1,%2,%3,%4};"
                         :: "r"(sa), "r"(u[0]), "r"(u[1]), "r"(u[2]), "r"(u[3]));
        }
    }

    // frag-read row base addresses
    uint32_t aRow0[2], aRow1[2];      // X rows (pitch XP)
    uint32_t gRow0[2], gRow1[2];      // G rows (pitch GPITCH)
    #pragma unroll
    for (int mt = 0; mt < 2; ++mt) {
        aRow0[mt] = sXb + (uint32_t)(wm + mt * 16 + g) * (XP * 4);
        aRow1[mt] = aRow0[mt] + 8 * XP * 4;
        gRow0[mt] = sXb + (uint32_t)(wm + mt * 16 + g) * (GPITCH * 4);
        gRow1[mt] = gRow0[mt] + 8 * GPITCH * 4;
    }

    // ================= stage 1: 4 phases of KC=64 =================
    float acc1[2][4][4];
    #pragma unroll
    for (int i = 0; i < 2; ++i)
        #pragma unroll
        for (int j = 0; j < 4; ++j)
            #pragma unroll
            for (int q = 0; q < 4; ++q) acc1[i][j][q] = 0.f;

    #pragma unroll 1
    for (int p = 0; p < 4; ++p) {
        asm volatile("cp.async.wait_group 1;\n");
        __syncthreads();
        fetch(p + 2);
        const uint32_t wbuf = sWb + (uint32_t)(p % 3) * (CHUNK_FLOATS * 4);
        const int kbase = p * 64;
        #pragma unroll
        for (int P = 0; P < 4; ++P) {
            uint32_t A0[2][4], A1[2][4], Bf[4][4];
            const int col  = ((kbase + P * 16 + tg4) ^ fg) << 2;
            const int colw = ((P * 16 + tg4) ^ fg) << 2;
            #pragma unroll
            for (int mt = 0; mt < 2; ++mt) {
                lds128(A0[mt], aRow0[mt] + col);
                lds128(A1[mt], aRow1[mt] + col);
            }
            #pragma unroll
            for (int nt = 0; nt < 4; ++nt)
                lds128(Bf[nt], wbuf + (uint32_t)(wn1 + nt * 8 + g) * (64 * 4) + colw);
            #pragma unroll
            for (int mt = 0; mt < 2; ++mt)
                #pragma unroll
                for (int nt = 0; nt < 4; ++nt) {
                    mma8(acc1[mt][nt], A0[mt][0], A1[mt][0], A0[mt][1], A1[mt][1],
                         Bf[nt][0], Bf[nt][1]);
                    mma8(acc1[mt][nt], A0[mt][2], A1[mt][2], A0[mt][3], A1[mt][3],
                         Bf[nt][2], Bf[nt][3]);
                }
        }
    }

    // ---- gate: acc1 -> G (packed+swizzled over Xs region) ----
    __syncthreads();   // all stage-1 X reads complete before overwrite
    {
        #pragma unroll
        for (int mt = 0; mt < 2; ++mt)
            #pragma unroll
            for (int nt = 0; nt < 4; ++nt) {
                const int t = wm + mt * 16 + g;
                const int o = wn1 + nt * 8 + 2 * tg;
                const int c0 = packc(o)     ^ fg;
                const int c1 = packc(o + 1) ^ fg;
                float* cc = acc1[mt][nt];
                sm[(size_t)t * GPITCH + c0]       = tf32f(gate_fn(cc[0]));
                sm[(size_t)t * GPITCH + c1]       = tf32f(gate_fn(cc[1]));
                sm[(size_t)(t + 8) * GPITCH + c0] = tf32f(gate_fn(cc[2]));
                sm[(size_t)(t + 8) * GPITCH + c1] = tf32f(gate_fn(cc[3]));
            }
    }

    // ================= stage 2: 4 phases of KC=32 =================
    float acc2[2][8][4];
    #pragma unroll
    for (int i = 0; i < 2; ++i)
        #pragma unroll
        for (int j = 0; j < 8; ++j)
            #pragma unroll
            for (int q = 0; q < 4; ++q) acc2[i][j][q] = 0.f;

    #pragma unroll 1
    for (int p = 4; p < 8; ++p) {
        if (p < 7) asm volatile("cp.async.wait_group 1;\n");
        else       asm volatile("cp.async.wait_group 0;\n");
        __syncthreads();   // also publishes gate stores at p==4
        if (p + 2 < 8) fetch(p + 2);
        const uint32_t wbuf = sWb + (uint32_t)(p % 3) * (CHUNK_FLOATS * 4);
        const int kb2 = (p - 4) * 32;
        #pragma unroll
        for (int P = 0; P < 2; ++P) {
            uint32_t A0[2][4], A1[2][4];
            const int col  = ((kb2 + P * 16 + tg4) ^ fg) << 2;
            const int colw = ((P * 16 + tg4) ^ fg) << 2;
            #pragma unroll
            for (int mt = 0; mt < 2; ++mt) {
                lds128(A0[mt], gRow0[mt] + col);
                lds128(A1[mt], gRow1[mt] + col);
            }
            #pragma unroll
            for (int half = 0; half < 2; ++half) {
                uint32_t Bf[4][4];
                #pragma unroll
                for (int q = 0; q < 4; ++q) {
                    const int nt = half * 4 + q;
                    lds128(Bf[q], wbuf + (uint32_t)(wn2 + nt * 8 + g) * (32 * 4) + colw);
                }
                #pragma unroll
                for (int mt = 0; mt < 2; ++mt)
                    #pragma unroll
                    for (int q = 0; q < 4; ++q) {
                        const int nt = half * 4 + q;
                        mma8(acc2[mt][nt], A0[mt][0], A1[mt][0], A0[mt][1], A1[mt][1],
                             Bf[q][0], Bf[q][1]);
                        mma8(acc2[mt][nt], A0[mt][2], A1[mt][2], A0[mt][3], A1[mt][3],
                             Bf[q][2], Bf[q][3]);
                    }
            }
        }
    }

    // ================= epilogue: transpose in weight area, coalesced stores =================
    __syncthreads();   // all weight-buffer reads complete
    float* ST = sm + X_FLOATS;
    #pragma unroll
    for (int h = 0; h < 2; ++h) {
        if ((wid >> 3) == h) {
            #pragma unroll
            for (int mt = 0; mt < 2; ++mt)
                #pragma unroll
                for (int nt = 0; nt < 8; ++nt) {
                    const int t = wm + mt * 16 + g;
                    const int o = wn2 + nt * 8 + 2 * tg - h * 128;
                    float* cc = acc2[mt][nt];
                    ST[(size_t)o * STP + t]           = cc[0];
                    ST[(size_t)(o + 1) * STP + t]     = cc[1];
                    ST[(size_t)o * STP + t + 8]       = cc[2];
                    ST[(size_t)(o + 1) * STP + t + 8] = cc[3];
                }
        }
        __syncthreads();

        const int t  = tid & 127;
        const int tt = t0 + t;
        if (h == 0) {
            if (tt < L) {
                for (int rr = tid >> 7; rr < 128; rr += 4)
                    xout[((size_t)b * 128 + rr) * L + tt] =
                        ST[(size_t)rr * STP + t] + __ldg(brs + rr) + xb[(size_t)rr * Tc + tt + d];
            }
        } else {
            if (tt >= sstart && tt < L) {
                for (int rr = tid >> 7; rr < 128; rr += 4)
                    skip[((size_t)b * 128 + rr) * SKIP_SIZE + (tt - sstart)] =
                        ST[(size_t)rr * STP + t] + __ldg(bsk + rr);
            }
        }
        __syncthreads();
    }
}

// ---------------- host launcher ----------------
extern "C" void kernel_launch(void* const* d_in, const int* in_sizes, int n_in,
                              void* d_out, int out_size) {
    (void)in_sizes; (void)n_in; (void)out_size;

    const float* x     = (const float*)d_in[0];
    const float* wdil  = (const float*)d_in[1];
    const float* wres  = (const float*)d_in[2];
    const float* bres  = (const float*)d_in[3];
    const float* wskip = (const float*)d_in[4];
    const float* bskip = (const float*)d_in[5];
    float* out = (float*)d_out;

    float *bufA, *bufB, *w1, *w2;
    cudaGetSymbolAddress((void**)&bufA, g_bufA);
    cudaGetSymbolAddress((void**)&bufB, g_bufB);
    cudaGetSymbolAddress((void**)&w1,   g_w1);
    cudaGetSymbolAddress((void**)&w2,   g_w2);

    cudaFuncSetAttribute(wavenet_block, cudaFuncAttributeMaxDynamicSharedMemorySize, SMEM_BYTES);

    const int n1 = NBLK * W1_BLK_FLOATS;
    const int n2 = NBLK * W2_BLK_FLOATS;
    prep_w1<<<(n1 + 255) / 256, 256>>>(wdil, w1, n1);
    prep_w2<<<(n2 + 255) / 256, 256>>>(wres, wskip, w2, n2);

    int Tc = T_START;
    const float* cur = x;
    float* nxt = bufA;
    for (int blk = 0; blk < NBLK; ++blk) {
        const int d = H_DIL[blk];
        const int L = Tc - d;
        dim3 grid((L + TN - 1) / TN, BATCH);
        wavenet_block<<<grid, NTHREADS, SMEM_BYTES>>>(
            cur, nxt,
            out + (size_t)blk * BATCH * RES_C * SKIP_SIZE,
            w1 + (size_t)blk * W1_BLK_FLOATS,
            w2 + (size_t)blk * W2_BLK_FLOATS,
            bres + blk * 128, bskip + blk * 128,
            Tc, d, L, L - SKIP_SIZE);
        cur = nxt;
        nxt = (nxt == bufA) ? bufB : bufA;
        Tc = L;
    }
}

// round 5
// speedup vs baseline: 2.4129x; 1.5258x over previous
#include <cuda_runtime.h>
#include <cstdint>
#include <cstddef>

#define RES_C     128
#define BATCH     4
#define T_START   8192
#define NBLK      40
#define SKIP_SIZE 4096

#define TN        64
#define NTHREADS  256            // 8 warps, 2 CTAs/SM

#define XP        256            // X row pitch (floats)
#define GPITCH    128            // G row pitch

#define X_FLOATS      (64 * XP)          // 16384 (64KB)
#define CHUNK_FLOATS  4096               // 16KB chunks
#define NBUF          3
#define SMEM_BYTES    ((X_FLOATS + NBUF * CHUNK_FLOATS) * 4)   // 114688 (112KB)

#define WBLK_FLOATS   (8 * CHUNK_FLOATS) // 32768 per stage-group per block

static const int H_DIL[NBLK] = {
    1,2,4,8,16,32,64,128,256,512,
    1,2,4,8,16,32,64,128,256,512,
    1,2,4,8,16,32,64,128,256,512,
    1,2,4,8,16,32,64,128,256,512};

// ---------------- device scratch ----------------
__device__ float g_bufA[BATCH * RES_C * T_START];
__device__ float g_bufB[BATCH * RES_C * T_START];
__device__ float g_w1[NBLK * WBLK_FLOATS];   // 8 chunks: [out128][KC32] packed+swizzled
__device__ float g_w2[NBLK * WBLK_FLOATS];   // 8 chunks: 0-3 res, 4-7 skip: [out128][KC32]

// ---------------- layout helpers ----------------
// pack within 16-k groups: k = 16P + tg + 4j  <->  c = 16P + 4tg + j
__host__ __device__ __forceinline__ int packc(int k) {
    return ((k >> 4) << 4) | ((k & 3) << 2) | ((k & 15) >> 2);
}
// per-row bank swizzle (uses only r&7; value <= 28 < 32-float row)
__host__ __device__ __forceinline__ int fsw(int r) {
    return ((r & 1) << 4) | ((r & 6) << 1);
}

__device__ __forceinline__ uint32_t tf32u(float x) {
    uint32_t u;
    asm("cvt.rna.tf32.f32 %0, %1;" : "=r"(u) : "f"(x));
    return u;
}
__device__ __forceinline__ float tf32f(float x) { return __uint_as_float(tf32u(x)); }

__device__ __forceinline__ void mma8(float c[4], uint32_t a0, uint32_t a1, uint32_t a2,
                                     uint32_t a3, uint32_t b0, uint32_t b1) {
    asm volatile(
        "mma.sync.aligned.m16n8k8.row.col.f32.tf32.tf32.f32 "
        "{%0,%1,%2,%3}, {%4,%5,%6,%7}, {%8,%9}, {%0,%1,%2,%3};\n"
        : "+f"(c[0]), "+f"(c[1]), "+f"(c[2]), "+f"(c[3])
        : "r"(a0), "r"(a1), "r"(a2), "r"(a3), "r"(b0), "r"(b1));
}

__device__ __forceinline__ void lds128(uint32_t r[4], uint32_t addr) {
    asm volatile("ld.shared.v4.b32 {%0,%1,%2,%3}, [%4];"
                 : "=r"(r[0]), "=r"(r[1]), "=r"(r[2]), "=r"(r[3]) : "r"(addr));
}

// tanh(y)*sigmoid(y) = (1-u)/(1+u^2) * (y>=0 ? 1 : -u),  u = exp(-|y|)
__device__ __forceinline__ float gate_fn(float y) {
    float u = __expf(-fabsf(y));
    float a = (1.f - u) * __frcp_rn(1.f + u * u);
    return (y >= 0.f) ? a : -u * a;
}

// ---------------- weight prep ----------------
__global__ void prep_w1(const float* __restrict__ w, float* __restrict__ out, int n) {
    int i = blockIdx.x * blockDim.x + threadIdx.x;
    if (i >= n) return;
    int kl  = i & 31;
    int o   = (i >> 5) & 127;
    int ch  = (i >> 12) & 7;
    int blk = i >> 15;
    int kg  = ch * 32 + kl;
    float v = (kg < 128) ? w[(((blk * 128 + o) * 128) + kg) * 2 + 0]
                         : w[(((blk * 128 + o) * 128) + (kg - 128)) * 2 + 1];
    out[(size_t)blk * WBLK_FLOATS + ch * CHUNK_FLOATS + o * 32 + (packc(kl) ^ fsw(o))] = tf32f(v);
}
__global__ void prep_w2(const float* __restrict__ wr, const float* __restrict__ ws,
                        float* __restrict__ out, int n) {
    int i = blockIdx.x * blockDim.x + threadIdx.x;
    if (i >= n) return;
    int kl  = i & 31;
    int o   = (i >> 5) & 127;
    int ch  = (i >> 12) & 7;
    int blk = i >> 15;
    float v = (ch < 4) ? wr[((blk * 128 + o) * 128) + ch * 32 + kl]
                       : ws[((blk * 128 + o) * 128) + (ch - 4) * 32 + kl];
    out[(size_t)blk * WBLK_FLOATS + ch * CHUNK_FLOATS + o * 32 + (packc(kl) ^ fsw(o))] = tf32f(v);
}

// ---------------- fused per-block kernel ----------------
__global__ __launch_bounds__(NTHREADS, 2)
void wavenet_block(const float* __restrict__ xin, float* __restrict__ xout,
                   float* __restrict__ skip,
                   const float* __restrict__ w1g, const float* __restrict__ w2g,
                   const float* __restrict__ brs, const float* __restrict__ bsk,
                   int Tc, int d, int L, int sstart)
{
    extern __shared__ float sm[];
    const uint32_t sXb = (uint32_t)__cvta_generic_to_shared(sm);
    const uint32_t sWb = sXb + X_FLOATS * 4;

    const int tid  = threadIdx.x;
    const int lane = tid & 31;
    const int wid  = tid >> 5;
    const int g    = lane >> 2;
    const int tg   = lane & 3;
    const int tg4  = tg << 2;
    const int fg   = fsw(g);
    const int t0   = blockIdx.x * TN;
    const int b    = blockIdx.y;

    const int wm = (wid & 1) * 32;    // time tile (2 groups)
    const int wn = (wid >> 1) * 32;   // out tile (4 groups)

    const bool full      = (t0 + TN <= L);
    const bool need_skip = (t0 + TN > sstart);
    const int  lastc     = need_skip ? 15 : 11;

    // ---- cp.async weight chunk fetch (linear 16KB) ----
    auto fetch = [&](int c) {
        const float* src = (c < 8) ? (w1g + c * CHUNK_FLOATS)
                                   : (w2g + (c - 8) * CHUNK_FLOATS);
        uint32_t dst = sWb + (uint32_t)(c % 3) * (CHUNK_FLOATS * 4);
        #pragma unroll
        for (int i = 0; i < 4; ++i) {
            int e = tid + i * NTHREADS;
            asm volatile("cp.async.cg.shared.global [%0], [%1], 16;\n"
                         :: "r"(dst + e * 16), "l"(src + e * 4));
        }
        asm volatile("cp.async.commit_group;\n");
    };

    fetch(0);
    fetch(1);

    // ---- X tile load: row t (64), logical k (256): k<128 -> x[k][tt], else x[k-128][tt+d]
    const float* xb = xin + (size_t)b * RES_C * Tc;
    {
        const int t   = tid & 63;
        const int grp = tid >> 6;           // 0..3, 64 k's each
        const int tt  = t0 + t;
        const int ft  = fsw(t);
        const uint32_t xrow = sXb + (uint32_t)t * (XP * 4);
        if (full) {
            #pragma unroll
            for (int idx = 0; idx < 16; ++idx) {
                const int kb    = grp * 64 + (idx >> 2) * 16 + (idx & 3);
                const int cbase = grp * 64 + (idx >> 2) * 16 + (idx & 3) * 4;
                uint32_t u[4];
                #pragma unroll
                for (int j = 0; j < 4; ++j) {
                    const int k = kb + 4 * j;
                    float v = (k < 128) ? xb[(size_t)k * Tc + tt]
                                        : xb[(size_t)(k - 128) * Tc + tt + d];
                    u[j] = tf32u(v);
                }
                asm volatile("st.shared.v4.b32 [%0], {%1,%2,%3,%4};"
                             :: "r"(xrow + (uint32_t)((cbase ^ ft) << 2)),
                                "r"(u[0]), "r"(u[1]), "r"(u[2]), "r"(u[3]));
            }
        } else {
            #pragma unroll
            for (int idx = 0; idx < 16; ++idx) {
                const int kb    = grp * 64 + (idx >> 2) * 16 + (idx & 3);
                const int cbase = grp * 64 + (idx >> 2) * 16 + (idx & 3) * 4;
                uint32_t u[4];
                #pragma unroll
                for (int j = 0; j < 4; ++j) {
                    const int k = kb + 4 * j;
                    float v = 0.f;
                    if (k < 128) { if (tt < Tc) v = xb[(size_t)k * Tc + tt]; }
                    else         { if (tt < L)  v = xb[(size_t)(k - 128) * Tc + tt + d]; }
                    u[j] = tf32u(v);
                }
                asm volatile("st.shared.v4.b32 [%0], {%1,%2,%3,%4};"
                             :: "r"(xrow + (uint32_t)((cbase ^ ft) << 2)),
                                "r"(u[0]), "r"(u[1]), "r"(u[2]), "r"(u[3]));
            }
        }
    }

    uint32_t aRow0[2], aRow1[2], gRow0[2], gRow1[2];
    #pragma unroll
    for (int mt = 0; mt < 2; ++mt) {
        aRow0[mt] = sXb + (uint32_t)(wm + mt * 16 + g) * (XP * 4);
        aRow1[mt] = aRow0[mt] + 8 * XP * 4;
        gRow0[mt] = sXb + (uint32_t)(wm + mt * 16 + g) * (GPITCH * 4);
        gRow1[mt] = gRow0[mt] + 8 * GPITCH * 4;
    }

    // ================= stage 1: 8 phases of KC=32 =================
    float acc1[2][4][4];
    #pragma unroll
    for (int i = 0; i < 2; ++i)
        #pragma unroll
        for (int j = 0; j < 4; ++j)
            #pragma unroll
            for (int q = 0; q < 4; ++q) acc1[i][j][q] = 0.f;

    #pragma unroll 1
    for (int p = 0; p < 8; ++p) {
        asm volatile("cp.async.wait_group 1;\n");
        __syncthreads();
        fetch(p + 2);
        const uint32_t wbuf = sWb + (uint32_t)(p % 3) * (CHUNK_FLOATS * 4);
        const int kbase = p * 32;
        #pragma unroll
        for (int P = 0; P < 2; ++P) {
            const int col  = ((kbase + P * 16 + tg4) ^ fg) << 2;
            const int colw = ((P * 16 + tg4) ^ fg) << 2;
            uint32_t A0[2][4], A1[2][4], Bf[4][4];
            #pragma unroll
            for (int mt = 0; mt < 2; ++mt) {
                lds128(A0[mt], aRow0[mt] + col);
                lds128(A1[mt], aRow1[mt] + col);
            }
            #pragma unroll
            for (int nt = 0; nt < 4; ++nt)
                lds128(Bf[nt], wbuf + (uint32_t)(wn + nt * 8 + g) * (32 * 4) + colw);
            #pragma unroll
            for (int mt = 0; mt < 2; ++mt)
                #pragma unroll
                for (int nt = 0; nt < 4; ++nt) {
                    mma8(acc1[mt][nt], A0[mt][0], A1[mt][0], A0[mt][1], A1[mt][1],
                         Bf[nt][0], Bf[nt][1]);
                    mma8(acc1[mt][nt], A0[mt][2], A1[mt][2], A0[mt][3], A1[mt][3],
                         Bf[nt][2], Bf[nt][3]);
                }
        }
    }

    // ---- gate: acc1 -> G (packed+swizzled over X region) ----
    __syncthreads();   // all stage-1 X reads complete
    #pragma unroll
    for (int mt = 0; mt < 2; ++mt)
        #pragma unroll
        for (int nt = 0; nt < 4; ++nt) {
            const int t = wm + mt * 16 + g;
            const int o = wn + nt * 8 + 2 * tg;
            const int c0 = packc(o)     ^ fsw(t);
            const int c1 = packc(o + 1) ^ fsw(t);
            float* cc = acc1[mt][nt];
            sm[(size_t)t * GPITCH + c0]       = tf32f(gate_fn(cc[0]));
            sm[(size_t)t * GPITCH + c1]       = tf32f(gate_fn(cc[1]));
            sm[(size_t)(t + 8) * GPITCH + c0] = tf32f(gate_fn(cc[2]));
            sm[(size_t)(t + 8) * GPITCH + c1] = tf32f(gate_fn(cc[3]));
        }

    // ================= stage 2a: res GEMM, 4 phases of KC=32 =================
    float acc2[2][4][4];
    #pragma unroll
    for (int i = 0; i < 2; ++i)
        #pragma unroll
        for (int j = 0; j < 4; ++j)
            #pragma unroll
            for (int q = 0; q < 4; ++q) acc2[i][j][q] = 0.f;

    #pragma unroll 1
    for (int p = 8; p < 12; ++p) {
        asm volatile("cp.async.wait_group 1;\n");
        __syncthreads();   // first iteration also publishes gate stores
        if (p + 2 <= lastc) fetch(p + 2);
        const uint32_t wbuf = sWb + (uint32_t)(p % 3) * (CHUNK_FLOATS * 4);
        const int kb = (p - 8) * 32;
        #pragma unroll
        for (int P = 0; P < 2; ++P) {
            const int col  = ((kb + P * 16 + tg4) ^ fg) << 2;
            const int colw = ((P * 16 + tg4) ^ fg) << 2;
            uint32_t A0[2][4], A1[2][4], Bf[4][4];
            #pragma unroll
            for (int mt = 0; mt < 2; ++mt) {
                lds128(A0[mt], gRow0[mt] + col);
                lds128(A1[mt], gRow1[mt] + col);
            }
            #pragma unroll
            for (int nt = 0; nt < 4; ++nt)
                lds128(Bf[nt], wbuf + (uint32_t)(wn + nt * 8 + g) * (32 * 4) + colw);
            #pragma unroll
            for (int mt = 0; mt < 2; ++mt)
                #pragma unroll
                for (int nt = 0; nt < 4; ++nt) {
                    mma8(acc2[mt][nt], A0[mt][0], A1[mt][0], A0[mt][1], A1[mt][1],
                         Bf[nt][0], Bf[nt][1]);
                    mma8(acc2[mt][nt], A0[mt][2], A1[mt][2], A0[mt][3], A1[mt][3],
                         Bf[nt][2], Bf[nt][3]);
                }
        }
    }

    // ---- res epilogue: direct STG from accumulators (sector-aligned row runs) ----
    #pragma unroll
    for (int mt = 0; mt < 2; ++mt)
        #pragma unroll
        for (int nt = 0; nt < 4; ++nt) {
            const int t = wm + mt * 16 + g;
            const int o = wn + nt * 8 + 2 * tg;
            const float b0 = __ldg(brs + o);
            const float b1 = __ldg(brs + o + 1);
            const size_t r0 = (size_t)(b * 128 + o) * L;
            const size_t x0 = (size_t)o * Tc;
            float* cc = acc2[mt][nt];
            if (full) {
                xout[r0 + t0 + t]         = cc[0] + b0 + xb[x0 + t0 + t + d];
                xout[r0 + L + t0 + t]     = cc[1] + b1 + xb[x0 + Tc + t0 + t + d];
                xout[r0 + t0 + t + 8]     = cc[2] + b0 + xb[x0 + t0 + t + 8 + d];
                xout[r0 + L + t0 + t + 8] = cc[3] + b1 + xb[x0 + Tc + t0 + t + 8 + d];
            } else {
                if (t0 + t < L) {
                    xout[r0 + t0 + t]     = cc[0] + b0 + xb[x0 + t0 + t + d];
                    xout[r0 + L + t0 + t] = cc[1] + b1 + xb[x0 + Tc + t0 + t + d];
                }
                if (t0 + t + 8 < L) {
                    xout[r0 + t0 + t + 8]     = cc[2] + b0 + xb[x0 + t0 + t + 8 + d];
                    xout[r0 + L + t0 + t + 8] = cc[3] + b1 + xb[x0 + Tc + t0 + t + 8 + d];
                }
            }
        }

    // ================= stage 2b: skip GEMM + epilogue (window CTAs only) =================
    if (need_skip) {
        float acc3[2][4][4];
        #pragma unroll
        for (int i = 0; i < 2; ++i)
            #pragma unroll
            for (int j = 0; j < 4; ++j)
                #pragma unroll
                for (int q = 0; q < 4; ++q) acc3[i][j][q] = 0.f;

        #pragma unroll 1
        for (int p = 12; p < 16; ++p) {
            if (p < 15) asm volatile("cp.async.wait_group 1;\n");
            else        asm volatile("cp.async.wait_group 0;\n");
            __syncthreads();
            if (p + 2 <= 15) fetch(p + 2);
            const uint32_t wbuf = sWb + (uint32_t)(p % 3) * (CHUNK_FLOATS * 4);
            const int kb = (p - 12) * 32;
            #pragma unroll
            for (int P = 0; P < 2; ++P) {
                const int col  = ((kb + P * 16 + tg4) ^ fg) << 2;
                const int colw = ((P * 16 + tg4) ^ fg) << 2;
                uint32_t A0[2][4], A1[2][4], Bf[4][4];
                #pragma unroll
                for (int mt = 0; mt < 2; ++mt) {
                    lds128(A0[mt], gRow0[mt] + col);
                    lds128(A1[mt], gRow1[mt] + col);
                }
                #pragma unroll
                for (int nt = 0; nt < 4; ++nt)
                    lds128(Bf[nt], wbuf + (uint32_t)(wn + nt * 8 + g) * (32 * 4) + colw);
                #pragma unroll
                for (int mt = 0; mt < 2; ++mt)
                    #pragma unroll
                    for (int nt = 0; nt < 4; ++nt) {
                        mma8(acc3[mt][nt], A0[mt][0], A1[mt][0], A0[mt][1], A1[mt][1],
                             Bf[nt][0], Bf[nt][1]);
                        mma8(acc3[mt][nt], A0[mt][2], A1[mt][2], A0[mt][3], A1[mt][3],
                             Bf[nt][2], Bf[nt][3]);
                    }
            }
        }

        const bool wfull = full && (t0 >= sstart);
        #pragma unroll
        for (int mt = 0; mt < 2; ++mt)
            #pragma unroll
            for (int nt = 0; nt < 4; ++nt) {
                const int t = wm + mt * 16 + g;
                const int o = wn + nt * 8 + 2 * tg;
                const float b0 = __ldg(bsk + o);
                const float b1 = __ldg(bsk + o + 1);
                const size_t r0 = (size_t)(b * 128 + o) * SKIP_SIZE - sstart;
                float* cc = acc3[mt][nt];
                if (wfull) {
                    skip[r0 + t0 + t]                 = cc[0] + b0;
                    skip[r0 + SKIP_SIZE + t0 + t]     = cc[1] + b1;
                    skip[r0 + t0 + t + 8]             = cc[2] + b0;
                    skip[r0 + SKIP_SIZE + t0 + t + 8] = cc[3] + b1;
                } else {
                    const int tt0 = t0 + t, tt1 = t0 + t + 8;
                    if (tt0 >= sstart && tt0 < L) {
                        skip[r0 + tt0]             = cc[0] + b0;
                        skip[r0 + SKIP_SIZE + tt0] = cc[1] + b1;
                    }
                    if (tt1 >= sstart && tt1 < L) {
                        skip[r0 + tt1]             = cc[2] + b0;
                        skip[r0 + SKIP_SIZE + tt1] = cc[3] + b1;
                    }
                }
            }
    }

    asm volatile("cp.async.wait_group 0;\n");   // drain before CTA exit
}

// ---------------- host launcher ----------------
extern "C" void kernel_launch(void* const* d_in, const int* in_sizes, int n_in,
                              void* d_out, int out_size) {
    (void)in_sizes; (void)n_in; (void)out_size;

    const float* x     = (const float*)d_in[0];
    const float* wdil  = (const float*)d_in[1];
    const float* wres  = (const float*)d_in[2];
    const float* bres  = (const float*)d_in[3];
    const float* wskip = (const float*)d_in[4];
    const float* bskip = (const float*)d_in[5];
    float* out = (float*)d_out;

    float *bufA, *bufB, *w1, *w2;
    cudaGetSymbolAddress((void**)&bufA, g_bufA);
    cudaGetSymbolAddress((void**)&bufB, g_bufB);
    cudaGetSymbolAddress((void**)&w1,   g_w1);
    cudaGetSymbolAddress((void**)&w2,   g_w2);

    cudaFuncSetAttribute(wavenet_block, cudaFuncAttributeMaxDynamicSharedMemorySize, SMEM_BYTES);

    const int n1 = NBLK * WBLK_FLOATS;
    prep_w1<<<(n1 + 255) / 256, 256>>>(wdil, w1, n1);
    prep_w2<<<(n1 + 255) / 256, 256>>>(wres, wskip, w2, n1);

    int Tc = T_START;
    const float* cur = x;
    float* nxt = bufA;
    for (int blk = 0; blk < NBLK; ++blk) {
        const int d = H_DIL[blk];
        const int L = Tc - d;
        dim3 grid((L + TN - 1) / TN, BATCH);
        wavenet_block<<<grid, NTHREADS, SMEM_BYTES>>>(
            cur, nxt,
            out + (size_t)blk * BATCH * RES_C * SKIP_SIZE,
            w1 + (size_t)blk * WBLK_FLOATS,
            w2 + (size_t)blk * WBLK_FLOATS,
            bres + blk * 128, bskip + blk * 128,
            Tc, d, L, L - SKIP_SIZE);
        cur = nxt;
        nxt = (nxt == bufA) ? bufB : bufA;
        Tc = L;
    }
}

// round 6
// speedup vs baseline: 2.8890x; 1.1973x over previous
#include <cuda_runtime.h>
#include <cstdint>
#include <cstddef>

#define RES_C     128
#define BATCH     4
#define T_START   8192
#define NBLK      40
#define SKIP_SIZE 4096

#define TN        64
#define NTHREADS  256            // 8 warps, 2 CTAs/SM

#define XPCH      128            // X/G row pitch (floats)

// smem regions (float offsets)
#define REGA      0              // X_a (32KB) -> stage-2 pair buf (even)
#define REGB      8192           // X_b (32KB) -> stage-2 pair buf (odd)
#define REGW      16384          // 3 x 16KB stage-1 weight bufs -> G (32KB)
#define SMEM_FLOATS 28672
#define SMEM_BYTES  (SMEM_FLOATS * 4)    // 114688 (112KB)

#define W1CHUNK   4096           // 16KB stage-1 chunk ([128o][32k])
#define W2PAIR    8192           // 32KB stage-2 pair  ([res 128x32][skip 128x32])
#define WBLK_FLOATS 32768        // per block per stage-group

static const int H_DIL[NBLK] = {
    1,2,4,8,16,32,64,128,256,512,
    1,2,4,8,16,32,64,128,256,512,
    1,2,4,8,16,32,64,128,256,512,
    1,2,4,8,16,32,64,128,256,512};

// ---------------- device scratch ----------------
__device__ float g_bufA[BATCH * RES_C * T_START];
__device__ float g_bufB[BATCH * RES_C * T_START];
__device__ float g_w1[NBLK * WBLK_FLOATS];   // 8 chunks [o128][k32] packed+swizzled
__device__ float g_w2[NBLK * WBLK_FLOATS];   // 4 pairs: [res 128x32 | skip 128x32]

// ---------------- layout helpers ----------------
__host__ __device__ __forceinline__ int packc(int k) {
    return ((k >> 4) << 4) | ((k & 3) << 2) | ((k & 15) >> 2);
}
__host__ __device__ __forceinline__ int fsw(int r) {
    return ((r & 1) << 4) | ((r & 6) << 1);
}

__device__ __forceinline__ uint32_t tf32u(float x) {
    uint32_t u;
    asm("cvt.rna.tf32.f32 %0, %1;" : "=r"(u) : "f"(x));
    return u;
}
__device__ __forceinline__ float tf32f(float x) { return __uint_as_float(tf32u(x)); }

__device__ __forceinline__ void mma8(float c[4], uint32_t a0, uint32_t a1, uint32_t a2,
                                     uint32_t a3, uint32_t b0, uint32_t b1) {
    asm volatile(
        "mma.sync.aligned.m16n8k8.row.col.f32.tf32.tf32.f32 "
        "{%0,%1,%2,%3}, {%4,%5,%6,%7}, {%8,%9}, {%0,%1,%2,%3};\n"
        : "+f"(c[0]), "+f"(c[1]), "+f"(c[2]), "+f"(c[3])
        : "r"(a0), "r"(a1), "r"(a2), "r"(a3), "r"(b0), "r"(b1));
}

__device__ __forceinline__ void lds128(uint32_t r[4], uint32_t addr) {
    asm volatile("ld.shared.v4.b32 {%0,%1,%2,%3}, [%4];"
                 : "=r"(r[0]), "=r"(r[1]), "=r"(r[2]), "=r"(r[3]) : "r"(addr));
}

__device__ __forceinline__ float gate_fn(float y) {
    float u = __expf(-fabsf(y));
    float a = (1.f - u) * __frcp_rn(1.f + u * u);
    return (y >= 0.f) ? a : -u * a;
}

#define CPWAIT(n) asm volatile("cp.async.wait_group " #n ";\n")

// ---------------- weight prep ----------------
__global__ void prep_w1(const float* __restrict__ w, float* __restrict__ out, int n) {
    int i = blockIdx.x * blockDim.x + threadIdx.x;
    if (i >= n) return;
    int kl  = i & 31;
    int o   = (i >> 5) & 127;
    int ch  = (i >> 12) & 7;
    int blk = i >> 15;
    int kg  = ch * 32 + kl;
    float v = (kg < 128) ? w[(((blk * 128 + o) * 128) + kg) * 2 + 0]
                         : w[(((blk * 128 + o) * 128) + (kg - 128)) * 2 + 1];
    out[(size_t)blk * WBLK_FLOATS + ch * W1CHUNK + o * 32 + (packc(kl) ^ fsw(o))] = tf32f(v);
}
// pairs: [pair p][res 128x32][skip 128x32]
__global__ void prep_w2(const float* __restrict__ wr, const float* __restrict__ ws,
                        float* __restrict__ out, int n) {
    int i = blockIdx.x * blockDim.x + threadIdx.x;
    if (i >= n) return;
    int kl  = i & 31;
    int o   = (i >> 5) & 127;
    int h   = (i >> 12) & 1;
    int pr  = (i >> 13) & 3;
    int blk = i >> 15;
    float v = (h == 0) ? wr[((blk * 128 + o) * 128) + pr * 32 + kl]
                       : ws[((blk * 128 + o) * 128) + pr * 32 + kl];
    out[(size_t)blk * WBLK_FLOATS + pr * W2PAIR + h * 4096 + o * 32 + (packc(kl) ^ fsw(o))]
        = tf32f(v);
}

// ---------------- fused per-block kernel ----------------
__global__ __launch_bounds__(NTHREADS, 2)
void wavenet_block(const float* __restrict__ xin, float* __restrict__ xout,
                   float* __restrict__ skip,
                   const float* __restrict__ w1g, const float* __restrict__ w2g,
                   const float* __restrict__ brs, const float* __restrict__ bsk,
                   int Tc, int d, int L, int sstart)
{
    extern __shared__ float sm[];
    const uint32_t sb = (uint32_t)__cvta_generic_to_shared(sm);

    const int tid  = threadIdx.x;
    const int lane = tid & 31;
    const int wid  = tid >> 5;
    const int g    = lane >> 2;
    const int tg   = lane & 3;
    const int tg4  = tg << 2;
    const int fg   = fsw(g);
    const int t0   = blockIdx.x * TN;
    const int b    = blockIdx.y;

    const int wm = (wid & 1) * 32;    // time tile
    const int wn = (wid >> 1) * 32;   // out tile

    const bool full      = (t0 + TN <= L);
    const bool need_skip = (t0 + TN > sstart);

    // ---- stage-1 weight chunk fetch (16KB into W rotation) ----
    auto fetch1 = [&](int c) {
        const float* src = w1g + c * W1CHUNK;
        uint32_t dst = sb + (REGW + (c % 3) * W1CHUNK) * 4;
        #pragma unroll
        for (int i = 0; i < 4; ++i) {
            int e = tid + i * NTHREADS;
            asm volatile("cp.async.cg.shared.global [%0], [%1], 16;\n"
                         :: "r"(dst + e * 16), "l"(src + e * 4));
        }
        asm volatile("cp.async.commit_group;\n");
    };
    // ---- stage-2 pair fetch (32KB into region A or B) ----
    auto fetch2 = [&](int p, int region) {
        const float* src = w2g + p * W2PAIR;
        uint32_t dst = sb + region * 4;
        #pragma unroll
        for (int i = 0; i < 8; ++i) {
            int e = tid + i * NTHREADS;
            asm volatile("cp.async.cg.shared.global [%0], [%1], 16;\n"
                         :: "r"(dst + e * 16), "l"(src + e * 4));
        }
        asm volatile("cp.async.commit_group;\n");
    };

    fetch1(0);
    fetch1(1);

    // ---- X tile load: X_a (regA) k 0..127 <- x[k][tt]; X_b (regB) k 0..127 <- x[k][tt+d]
    const float* xb = xin + (size_t)b * RES_C * Tc;
    {
        const int t    = tid & 63;
        const int grp  = tid >> 6;            // 0..3
        const int half = grp >> 1;            // 0 -> X_a, 1 -> X_b
        const int kof  = (grp & 1) * 64;      // col base within region
        const int tt   = t0 + t;
        const int ft   = fsw(t);
        const uint32_t xrow = sb + ((half ? REGB : REGA) + t * XPCH) * 4;
        const float* base = xb + (half ? d : 0);
        const bool ok_t = half ? (tt < L) : (tt < Tc);
        if (full) {
            #pragma unroll
            for (int idx = 0; idx < 16; ++idx) {
                const int kb    = kof + (idx >> 2) * 16 + (idx & 3);
                const int cbase = kof + (idx >> 2) * 16 + (idx & 3) * 4;
                uint32_t u[4];
                #pragma unroll
                for (int j = 0; j < 4; ++j)
                    u[j] = tf32u(base[(size_t)(kb + 4 * j) * Tc + tt]);
                asm volatile("st.shared.v4.b32 [%0], {%1,%2,%3,%4};"
                             :: "r"(xrow + (uint32_t)((cbase ^ ft) << 2)),
                                "r"(u[0]), "r"(u[1]), "r"(u[2]), "r"(u[3]));
            }
        } else {
            #pragma unroll
            for (int idx = 0; idx < 16; ++idx) {
                const int kb    = kof + (idx >> 2) * 16 + (idx & 3);
                const int cbase = kof + (idx >> 2) * 16 + (idx & 3) * 4;
                uint32_t u[4];
                #pragma unroll
                for (int j = 0; j < 4; ++j) {
                    float v = ok_t ? base[(size_t)(kb + 4 * j) * Tc + tt] : 0.f;
                    u[j] = tf32u(v);
                }
                asm volatile("st.shared.v4.b32 [%0], {%1,%2,%3,%4};"
                             :: "r"(xrow + (uint32_t)((cbase ^ ft) << 2)),
                                "r"(u[0]), "r"(u[1]), "r"(u[2]), "r"(u[3]));
            }
        }
    }

    uint32_t aRowA[2], aRowB[2], gRow[2];
    #pragma unroll
    for (int mt = 0; mt < 2; ++mt) {
        const int r = wm + mt * 16 + g;
        aRowA[mt] = sb + (REGA + r * XPCH) * 4;
        aRowB[mt] = sb + (REGB + r * XPCH) * 4;
        gRow[mt]  = sb + (REGW + r * XPCH) * 4;
    }

    float acc1[2][4][4];
    #pragma unroll
    for (int i = 0; i < 2; ++i)
        #pragma unroll
        for (int j = 0; j < 4; ++j)
            #pragma unroll
            for (int q = 0; q < 4; ++q) acc1[i][j][q] = 0.f;

    // one stage-1 compute phase: chunk c, A rows from rowsLo/Hi (+8*pitch), k-cols kb..kb+31
    auto s1_phase = [&](int c, const uint32_t aRow[2], int kb) {
        const uint32_t wbuf = sb + (REGW + (c % 3) * W1CHUNK) * 4;
        #pragma unroll
        for (int P = 0; P < 2; ++P) {
            const int col  = ((kb + P * 16 + tg4) ^ fg) << 2;
            const int colw = ((P * 16 + tg4) ^ fg) << 2;
            uint32_t A0[2][4], A1[2][4], Bf[4][4];
            #pragma unroll
            for (int mt = 0; mt < 2; ++mt) {
                lds128(A0[mt], aRow[mt] + col);
                lds128(A1[mt], aRow[mt] + 8 * XPCH * 4 + col);
            }
            #pragma unroll
            for (int nt = 0; nt < 4; ++nt)
                lds128(Bf[nt], wbuf + (uint32_t)(wn + nt * 8 + g) * (32 * 4) + colw);
            #pragma unroll
            for (int mt = 0; mt < 2; ++mt)
                #pragma unroll
                for (int nt = 0; nt < 4; ++nt) {
                    mma8(acc1[mt][nt], A0[mt][0], A1[mt][0], A0[mt][1], A1[mt][1],
                         Bf[nt][0], Bf[nt][1]);
                    mma8(acc1[mt][nt], A0[mt][2], A1[mt][2], A0[mt][3], A1[mt][3],
                         Bf[nt][2], Bf[nt][3]);
                }
        }
    };

    // ===== stage 1, first half: chunks 0-3 on X_a =====
    #pragma unroll 1
    for (int p = 0; p < 4; ++p) {
        CPWAIT(1);
        __syncthreads();
        fetch1(p + 2);                 // c2..c5
        s1_phase(p, aRowA, p * 32);
    }
    // ===== stage 1, second half: chunks 4-7 on X_b; inject pair-0 prefetch into regA =====
    {
        // q=0 (c4)
        CPWAIT(1);                     // ensures c4 (all but c5)
        __syncthreads();               // regA reads finished (phase 3 done by all)
        fetch1(6);
        fetch2(0, REGA);               // long-range prefetch of stage-2 pair 0
        s1_phase(4, aRowB, 0);
        // q=1 (c5)
        CPWAIT(2);                     // all but {c6, P0} -> ensures c5
        __syncthreads();
        fetch1(7);
        s1_phase(5, aRowB, 32);
        // q=2 (c6)
        CPWAIT(2);                     // all but {P0, c7} -> ensures c6
        __syncthreads();
        s1_phase(6, aRowB, 64);
        // q=3 (c7)
        CPWAIT(0);                     // c7 + P0 both done
        __syncthreads();
        s1_phase(7, aRowB, 96);
    }

    // ---- pair-1 prefetch into regB (free now), then gate into G (W region) ----
    __syncthreads();                   // all stage-1 reads of regB / W complete
    fetch2(1, REGB);
    #pragma unroll
    for (int mt = 0; mt < 2; ++mt)
        #pragma unroll
        for (int nt = 0; nt < 4; ++nt) {
            const int t = wm + mt * 16 + g;
            const int o = wn + nt * 8 + 2 * tg;
            const int c0 = packc(o)     ^ fsw(t);
            const int c1 = packc(o + 1) ^ fsw(t);
            float* cc = acc1[mt][nt];
            sm[REGW + t * XPCH + c0]       = tf32f(gate_fn(cc[0]));
            sm[REGW + t * XPCH + c1]       = tf32f(gate_fn(cc[1]));
            sm[REGW + (t + 8) * XPCH + c0] = tf32f(gate_fn(cc[2]));
            sm[REGW + (t + 8) * XPCH + c1] = tf32f(gate_fn(cc[3]));
        }
    __syncthreads();                   // publish G; P0 visible

    // ===== stage 2: 4 merged phases (res + skip share G fragments) =====
    float acc2[2][4][4], acc3[2][4][4];
    #pragma unroll
    for (int i = 0; i < 2; ++i)
        #pragma unroll
        for (int j = 0; j < 4; ++j)
            #pragma unroll
            for (int q = 0; q < 4; ++q) { acc2[i][j][q] = 0.f; acc3[i][j][q] = 0.f; }

    #pragma unroll 1
    for (int s = 0; s < 4; ++s) {
        if (s > 0) {
            CPWAIT(0);                 // pair s ready (prefetched >= 1 phase ago)
            __syncthreads();           // previous buffer reads done; visibility
            if (s == 1) fetch2(2, REGA);
            if (s == 2) fetch2(3, REGB);
        }
        const uint32_t pbuf = sb + ((s & 1) ? REGB : REGA) * 4;
        const int kb = s * 32;
        #pragma unroll
        for (int P = 0; P < 2; ++P) {
            const int col  = ((kb + P * 16 + tg4) ^ fg) << 2;
            const int colw = ((P * 16 + tg4) ^ fg) << 2;
            uint32_t A0[2][4], A1[2][4], Bf[4][4];
            #pragma unroll
            for (int mt = 0; mt < 2; ++mt) {
                lds128(A0[mt], gRow[mt] + col);
                lds128(A1[mt], gRow[mt] + 8 * XPCH * 4 + col);
            }
            #pragma unroll
            for (int nt = 0; nt < 4; ++nt)
                lds128(Bf[nt], pbuf + (uint32_t)(wn + nt * 8 + g) * (32 * 4) + colw);
            #pragma unroll
            for (int mt = 0; mt < 2; ++mt)
                #pragma unroll
                for (int nt = 0; nt < 4; ++nt) {
                    mma8(acc2[mt][nt], A0[mt][0], A1[mt][0], A0[mt][1], A1[mt][1],
                         Bf[nt][0], Bf[nt][1]);
                    mma8(acc2[mt][nt], A0[mt][2], A1[mt][2], A0[mt][3], A1[mt][3],
                         Bf[nt][2], Bf[nt][3]);
                }
            if (need_skip) {
                #pragma unroll
                for (int nt = 0; nt < 4; ++nt)
                    lds128(Bf[nt], pbuf + 4096 * 4 + (uint32_t)(wn + nt * 8 + g) * (32 * 4) + colw);
                #pragma unroll
                for (int mt = 0; mt < 2; ++mt)
                    #pragma unroll
                    for (int nt = 0; nt < 4; ++nt) {
                        mma8(acc3[mt][nt], A0[mt][0], A1[mt][0], A0[mt][1], A1[mt][1],
                             Bf[nt][0], Bf[nt][1]);
                        mma8(acc3[mt][nt], A0[mt][2], A1[mt][2], A0[mt][3], A1[mt][3],
                             Bf[nt][2], Bf[nt][3]);
                    }
            }
        }
    }

    // ---- res epilogue: direct STG from accumulators ----
    #pragma unroll
    for (int mt = 0; mt < 2; ++mt)
        #pragma unroll
        for (int nt = 0; nt < 4; ++nt) {
            const int t = wm + mt * 16 + g;
            const int o = wn + nt * 8 + 2 * tg;
            const float b0 = __ldg(brs + o);
            const float b1 = __ldg(brs + o + 1);
            const size_t r0 = (size_t)(b * 128 + o) * L;
            const size_t x0 = (size_t)o * Tc;
            float* cc = acc2[mt][nt];
            if (full) {
                xout[r0 + t0 + t]         = cc[0] + b0 + xb[x0 + t0 + t + d];
                xout[r0 + L + t0 + t]     = cc[1] + b1 + xb[x0 + Tc + t0 + t + d];
                xout[r0 + t0 + t + 8]     = cc[2] + b0 + xb[x0 + t0 + t + 8 + d];
                xout[r0 + L + t0 + t + 8] = cc[3] + b1 + xb[x0 + Tc + t0 + t + 8 + d];
            } else {
                if (t0 + t < L) {
                    xout[r0 + t0 + t]     = cc[0] + b0 + xb[x0 + t0 + t + d];
                    xout[r0 + L + t0 + t] = cc[1] + b1 + xb[x0 + Tc + t0 + t + d];
                }
                if (t0 + t + 8 < L) {
                    xout[r0 + t0 + t + 8]     = cc[2] + b0 + xb[x0 + t0 + t + 8 + d];
                    xout[r0 + L + t0 + t + 8] = cc[3] + b1 + xb[x0 + Tc + t0 + t + 8 + d];
                }
            }
        }

    // ---- skip epilogue ----
    if (need_skip) {
        const bool wfull = full && (t0 >= sstart);
        #pragma unroll
        for (int mt = 0; mt < 2; ++mt)
            #pragma unroll
            for (int nt = 0; nt < 4; ++nt) {
                const int t = wm + mt * 16 + g;
                const int o = wn + nt * 8 + 2 * tg;
                const float b0 = __ldg(bsk + o);
                const float b1 = __ldg(bsk + o + 1);
                const size_t r0 = (size_t)(b * 128 + o) * SKIP_SIZE - sstart;
                float* cc = acc3[mt][nt];
                if (wfull) {
                    skip[r0 + t0 + t]                 = cc[0] + b0;
                    skip[r0 + SKIP_SIZE + t0 + t]     = cc[1] + b1;
                    skip[r0 + t0 + t + 8]             = cc[2] + b0;
                    skip[r0 + SKIP_SIZE + t0 + t + 8] = cc[3] + b1;
                } else {
                    const int tt0 = t0 + t, tt1 = t0 + t + 8;
                    if (tt0 >= sstart && tt0 < L) {
                        skip[r0 + tt0]             = cc[0] + b0;
                        skip[r0 + SKIP_SIZE + tt0] = cc[1] + b1;
                    }
                    if (tt1 >= sstart && tt1 < L) {
                        skip[r0 + tt1]             = cc[2] + b0;
                        skip[r0 + SKIP_SIZE + tt1] = cc[3] + b1;
                    }
                }
            }
    }

    CPWAIT(0);   // drain before CTA exit
}

// ---------------- host launcher ----------------
extern "C" void kernel_launch(void* const* d_in, const int* in_sizes, int n_in,
                              void* d_out, int out_size) {
    (void)in_sizes; (void)n_in; (void)out_size;

    const float* x     = (const float*)d_in[0];
    const float* wdil  = (const float*)d_in[1];
    const float* wres  = (const float*)d_in[2];
    const float* bres  = (const float*)d_in[3];
    const float* wskip = (const float*)d_in[4];
    const float* bskip = (const float*)d_in[5];
    float* out = (float*)d_out;

    float *bufA, *bufB, *w1, *w2;
    cudaGetSymbolAddress((void**)&bufA, g_bufA);
    cudaGetSymbolAddress((void**)&bufB, g_bufB);
    cudaGetSymbolAddress((void**)&w1,   g_w1);
    cudaGetSymbolAddress((void**)&w2,   g_w2);

    cudaFuncSetAttribute(wavenet_block, cudaFuncAttributeMaxDynamicSharedMemorySize, SMEM_BYTES);

    const int n1 = NBLK * WBLK_FLOATS;
    prep_w1<<<(n1 + 255) / 256, 256>>>(wdil, w1, n1);
    prep_w2<<<(n1 + 255) / 256, 256>>>(wres, wskip, w2, n1);

    int Tc = T_START;
    const float* cur = x;
    float* nxt = bufA;
    for (int blk = 0; blk < NBLK; ++blk) {
        const int d = H_DIL[blk];
        const int L = Tc - d;
        dim3 grid((L + TN - 1) / TN, BATCH);
        wavenet_block<<<grid, NTHREADS, SMEM_BYTES>>>(
            cur, nxt,
            out + (size_t)blk * BATCH * RES_C * SKIP_SIZE,
            w1 + (size_t)blk * WBLK_FLOATS,
            w2 + (size_t)blk * WBLK_FLOATS,
            bres + blk * 128, bskip + blk * 128,
            Tc, d, L, L - SKIP_SIZE);
        cur = nxt;
        nxt = (nxt == bufA) ? bufB : bufA;
        Tc = L;
    }
}